// round 1
// baseline (speedup 1.0000x reference)
#include <cuda_runtime.h>

// Problem dims (fixed by the reference)
#define BATCH 16384
#define DIM   1024
#define ADIM  1024

// GEMM tiling
#define BM 128
#define BN 128
#define BK 16
#define TM 8
#define TN 8
#define NTHREADS 256

// Scratch (device globals — allocation-free per harness rules)
__device__ float g_K[BATCH * ADIM];
__device__ float g_V[BATCH * ADIM];
__device__ float g_R[BATCH * ADIM];
__device__ float g_rwkv[BATCH * ADIM];

// ---------------------------------------------------------------------------
// GEMM core: C[B, N] = A[B, K] @ W[K, N], optional fused token-shift mixing
// of the A operand:  a = x*mix + last_x*(1-mix)
// ---------------------------------------------------------------------------
template <bool MIX>
__device__ __forceinline__ void gemm_tile(
    const float* __restrict__ X, const float* __restrict__ LX,
    const float* __restrict__ mixv,   // [K] broadcast row (only if MIX)
    const float* __restrict__ W,      // [K, N] row-major
    float* __restrict__ C,            // [B, N] row-major
    int Kdim, int Ndim)
{
    __shared__ float As[BK][BM];   // k-major (transposed) for the compute loop
    __shared__ float Bs[BK][BN];

    const int tid = threadIdx.x;

    // A-tile load mapping: 4 float4s per k-row group
    const int aRow = tid >> 2;            // 0..63 (m within tile; +64 second pass)
    const int aCol = (tid & 3) << 2;      // k offset {0,4,8,12}
    // B-tile load mapping
    const int bRow = tid >> 5;            // 0..7 (k; +8 second pass)
    const int bCol = (tid & 31) << 2;     // n offset

    const int row0 = blockIdx.y * BM;
    const int col0 = blockIdx.x * BN;

    const int ty = tid >> 4;              // 0..15 -> m sub-tile
    const int tx = tid & 15;              // 0..15 -> n sub-tile

    float acc[TM][TN];
#pragma unroll
    for (int i = 0; i < TM; i++)
#pragma unroll
        for (int j = 0; j < TN; j++) acc[i][j] = 0.f;

    for (int k0 = 0; k0 < Kdim; k0 += BK) {
        // ---- load A tile (with optional mixing) ----
#pragma unroll
        for (int r = 0; r < 2; r++) {
            const int m = aRow + r * 64;
            const long gA = (long)(row0 + m) * Kdim + k0 + aCol;
            float4 xv = *(const float4*)(X + gA);
            float4 av;
            if (MIX) {
                float4 lv = *(const float4*)(LX + gA);
                float4 mv = *(const float4*)(mixv + k0 + aCol);
                av.x = fmaf(xv.x - lv.x, mv.x, lv.x);
                av.y = fmaf(xv.y - lv.y, mv.y, lv.y);
                av.z = fmaf(xv.z - lv.z, mv.z, lv.z);
                av.w = fmaf(xv.w - lv.w, mv.w, lv.w);
            } else {
                av = xv;
            }
            As[aCol + 0][m] = av.x;
            As[aCol + 1][m] = av.y;
            As[aCol + 2][m] = av.z;
            As[aCol + 3][m] = av.w;
        }
        // ---- load B tile ----
#pragma unroll
        for (int r = 0; r < 2; r++) {
            const int kk = bRow + r * 8;
            *(float4*)&Bs[kk][bCol] =
                *(const float4*)(W + (long)(k0 + kk) * Ndim + col0 + bCol);
        }
        __syncthreads();

        // ---- compute ----
#pragma unroll
        for (int kk = 0; kk < BK; kk++) {
            float ra[TM], rb[TN];
#pragma unroll
            for (int i = 0; i < TM; i++) ra[i] = As[kk][ty * TM + i];
#pragma unroll
            for (int j = 0; j < TN; j++) rb[j] = Bs[kk][tx * TN + j];
#pragma unroll
            for (int i = 0; i < TM; i++)
#pragma unroll
                for (int j = 0; j < TN; j++)
                    acc[i][j] = fmaf(ra[i], rb[j], acc[i][j]);
        }
        __syncthreads();
    }

    // ---- epilogue: vectorized stores ----
#pragma unroll
    for (int i = 0; i < TM; i++) {
        const long base = (long)(row0 + ty * TM + i) * Ndim + col0 + tx * TN;
#pragma unroll
        for (int j = 0; j < TN; j += 4) {
            float4 v = make_float4(acc[i][j], acc[i][j + 1], acc[i][j + 2], acc[i][j + 3]);
            *(float4*)(C + base + j) = v;
        }
    }
}

// Three fused projections: z=0 -> K, z=1 -> V, z=2 -> R(pre-sigmoid)
__global__ void __launch_bounds__(NTHREADS)
proj3_kernel(const float* __restrict__ X, const float* __restrict__ LX,
             const float* __restrict__ mk, const float* __restrict__ mv,
             const float* __restrict__ mr,
             const float* __restrict__ Wk, const float* __restrict__ Wv,
             const float* __restrict__ Wr)
{
    const float* mix;
    const float* W;
    float* C;
    if (blockIdx.z == 0)      { mix = mk; W = Wk; C = g_K; }
    else if (blockIdx.z == 1) { mix = mv; W = Wv; C = g_V; }
    else                      { mix = mr; W = Wr; C = g_R; }
    gemm_tile<true>(X, LX, mix, W, C, DIM, ADIM);
}

// Output projection: hidden = rwkv @ Wout
__global__ void __launch_bounds__(NTHREADS)
outproj_kernel(const float* __restrict__ Wout, float* __restrict__ hidden)
{
    gemm_tile<false>(g_rwkv, nullptr, nullptr, Wout, hidden, ADIM, DIM);
}

// ---------------------------------------------------------------------------
// Elementwise RWKV recurrence: consumes g_K/g_V/g_R, produces g_rwkv and
// num/den outputs directly.
// ---------------------------------------------------------------------------
__global__ void __launch_bounds__(256)
rwkv_ew_kernel(const float* __restrict__ last_num, const float* __restrict__ last_den,
               const float* __restrict__ decay, const float* __restrict__ bonus,
               float* __restrict__ num_out, float* __restrict__ den_out)
{
    const long i = ((long)blockIdx.x * 256 + threadIdx.x) * 4;
    const int a = (int)(i & (ADIM - 1));   // column index (i is 4-aligned, ADIM pow2)

    float4 kk = *(const float4*)(g_K + i);
    float4 vv = *(const float4*)(g_V + i);
    float4 rp = *(const float4*)(g_R + i);
    float4 ln = *(const float4*)(last_num + i);
    float4 ld = *(const float4*)(last_den + i);
    float4 bo = *(const float4*)(bonus + a);
    float4 de = *(const float4*)(decay + a);

    float4 rw, no, dn;
    {
        const float* kp = &kk.x; const float* vp = &vv.x; const float* rpp = &rp.x;
        const float* lnp = &ln.x; const float* ldp = &ld.x;
        const float* bop = &bo.x; const float* dep = &de.x;
        float* rwp = &rw.x; float* nop = &no.x; float* dnp = &dn.x;
#pragma unroll
        for (int t = 0; t < 4; t++) {
            float k = kp[t], v = vp[t];
            float ebk = expf(bop[t] + k);
            float wkv = (lnp[t] + ebk * v) / (ldp[t] + ebk);
            float r = 1.0f / (1.0f + expf(-rpp[t]));
            rwp[t] = r * wkv;
            float w = expf(-expf(dep[t]));
            float ek = expf(k);
            nop[t] = w * lnp[t] + ek * v;
            dnp[t] = w * ldp[t] + ek;
        }
    }
    *(float4*)(g_rwkv + i)   = rw;
    *(float4*)(num_out + i)  = no;
    *(float4*)(den_out + i)  = dn;
}

// ---------------------------------------------------------------------------
// Launch
// Inputs (metadata order): x, last_x, last_num, last_den, mix_k, mix_v, mix_r,
//                          decay, bonus, Wk, Wv, Wr, Wout
// Output: concat(hidden[B,D], x[B,D], num[B,A], den[B,A]) as float32
// ---------------------------------------------------------------------------
extern "C" void kernel_launch(void* const* d_in, const int* in_sizes, int n_in,
                              void* d_out, int out_size)
{
    const float* x        = (const float*)d_in[0];
    const float* last_x   = (const float*)d_in[1];
    const float* last_num = (const float*)d_in[2];
    const float* last_den = (const float*)d_in[3];
    const float* mix_k    = (const float*)d_in[4];
    const float* mix_v    = (const float*)d_in[5];
    const float* mix_r    = (const float*)d_in[6];
    const float* decay    = (const float*)d_in[7];
    const float* bonus    = (const float*)d_in[8];
    const float* Wk       = (const float*)d_in[9];
    const float* Wv       = (const float*)d_in[10];
    const float* Wr       = (const float*)d_in[11];
    const float* Wout     = (const float*)d_in[12];

    float* out = (float*)d_out;
    const long BD = (long)BATCH * DIM;     // == BATCH*ADIM
    float* hidden_out = out;               // [B, D]
    float* x_out      = out + BD;          // [B, D]
    float* num_out    = out + 2 * BD;      // [B, A]
    float* den_out    = out + 3 * BD;      // [B, A]

    dim3 block(NTHREADS);

    // 1) K/V/R projections with fused mixing
    dim3 grid1(ADIM / BN, BATCH / BM, 3);
    proj3_kernel<<<grid1, block>>>(x, last_x, mix_k, mix_v, mix_r, Wk, Wv, Wr);

    // 2) Elementwise recurrence -> g_rwkv, num, den
    long nvec = (long)BATCH * ADIM / 4;
    rwkv_ew_kernel<<<(unsigned)(nvec / 256), 256>>>(last_num, last_den, decay, bonus,
                                                    num_out, den_out);

    // 3) hidden = rwkv @ Wout
    dim3 grid2(DIM / BN, BATCH / BM, 1);
    outproj_kernel<<<grid2, block>>>(Wout, hidden_out);

    // 4) passthrough x
    cudaMemcpyAsync(x_out, x, BD * sizeof(float), cudaMemcpyDeviceToDevice);
}

// round 2
// speedup vs baseline: 3.5352x; 3.5352x over previous
#include <cuda_runtime.h>

// Problem dims (fixed)
#define BATCH 16384
#define DIM   1024
#define ADIM  1024
#define KDIM  1024   // GEMM K (== DIM == ADIM)
#define NDIM  1024   // GEMM N

// GEMM tiling
#define BM 128
#define BN 128
#define BK 32
#define NTHREADS 256
#define ASTRIDE 36    // BK + 4 pad (floats)  -> conflict-free frag reads
#define BSTRIDE 136   // BN + 8 pad (floats)  -> conflict-free frag reads
#define ATILE_F (BM * ASTRIDE)   // 4608 floats
#define BTILE_F (BK * BSTRIDE)   // 4352 floats
#define SMEM_BYTES (2 * (ATILE_F + BTILE_F) * 4)   // 71680

// Scratch (device globals — allocation-free per harness rules)
__device__ float g_xk[BATCH * DIM];
__device__ float g_xv[BATCH * DIM];
__device__ float g_xr[BATCH * DIM];
__device__ float g_K[BATCH * ADIM];
__device__ float g_V[BATCH * ADIM];
__device__ float g_R[BATCH * ADIM];
__device__ float g_rwkv[BATCH * ADIM];
__device__ float g_W[4][KDIM * NDIM];   // tf32-rounded Wk, Wv, Wr, Wout

// ---------------------------------------------------------------------------
// helpers
// ---------------------------------------------------------------------------
__device__ __forceinline__ float tf32_rna(float x) {
    unsigned u;
    asm("cvt.rna.tf32.f32 %0, %1;" : "=r"(u) : "f"(x));
    return __uint_as_float(u);
}

__device__ __forceinline__ void cp_async16(void* smem_ptr, const void* gmem_ptr) {
    unsigned s = (unsigned)__cvta_generic_to_shared(smem_ptr);
    asm volatile("cp.async.cg.shared.global [%0], [%1], 16;\n" :: "r"(s), "l"(gmem_ptr));
}
__device__ __forceinline__ void cp_commit() {
    asm volatile("cp.async.commit_group;\n");
}
template <int N>
__device__ __forceinline__ void cp_wait() {
    asm volatile("cp.async.wait_group %0;\n" :: "n"(N));
}

__device__ __forceinline__ void mma_tf32(float4& d, const unsigned a[4], const unsigned b[2]) {
    asm volatile(
        "mma.sync.aligned.m16n8k8.row.col.f32.tf32.tf32.f32 "
        "{%0,%1,%2,%3}, {%4,%5,%6,%7}, {%8,%9}, {%0,%1,%2,%3};\n"
        : "+f"(d.x), "+f"(d.y), "+f"(d.z), "+f"(d.w)
        : "r"(a[0]), "r"(a[1]), "r"(a[2]), "r"(a[3]), "r"(b[0]), "r"(b[1]));
}

// ---------------------------------------------------------------------------
// tf32 GEMM: C[16384 or BATCH, 1024] = A[., 1024] @ W[1024, 1024]
// A and W are pre-rounded to tf32 values stored as f32.
// blockIdx.z selects which (A, W, C) triple (for the fused K/V/R launch).
// ---------------------------------------------------------------------------
__global__ void __launch_bounds__(NTHREADS, 2)
gemm_tf32_kernel(const float* __restrict__ A0, const float* __restrict__ A1,
                 const float* __restrict__ A2,
                 const float* __restrict__ B0, const float* __restrict__ B1,
                 const float* __restrict__ B2,
                 float* __restrict__ C0, float* __restrict__ C1,
                 float* __restrict__ C2)
{
    const float* A;
    const float* B;
    float* C;
    if (blockIdx.z == 0)      { A = A0; B = B0; C = C0; }
    else if (blockIdx.z == 1) { A = A1; B = B1; C = C1; }
    else                      { A = A2; B = B2; C = C2; }

    extern __shared__ float smem[];
    float* As = smem;                       // 2 stages of ATILE_F
    float* Bs = smem + 2 * ATILE_F;         // 2 stages of BTILE_F

    const int tid  = threadIdx.x;
    const int lane = tid & 31;
    const int grp  = lane >> 2;     // 0..7
    const int tin  = lane & 3;      // 0..3
    const int warp = tid >> 5;      // 0..7
    const int wm   = warp & 1;      // 0..1  -> 64-row slab
    const int wn   = warp >> 1;     // 0..3  -> 32-col slab

    const int row0 = blockIdx.y * BM;
    const int col0 = blockIdx.x * BN;

    // load mappings
    const int a_row   = tid >> 3;          // 0..31 (+32*r)
    const int a_chunk = (tid & 7) * 4;     // float offset within k
    const int b_row   = tid >> 5;          // 0..7 (+8*r)
    const int b_chunk = (tid & 31) * 4;

    float4 acc[4][4];
#pragma unroll
    for (int i = 0; i < 4; i++)
#pragma unroll
        for (int j = 0; j < 4; j++) acc[i][j] = make_float4(0.f, 0.f, 0.f, 0.f);

    // ---- tile loader ----
    auto load_tiles = [&](int k0, int stage) {
        float* As_s = As + stage * ATILE_F;
        float* Bs_s = Bs + stage * BTILE_F;
#pragma unroll
        for (int r = 0; r < 4; r++) {
            int row = a_row + 32 * r;
            cp_async16(As_s + row * ASTRIDE + a_chunk,
                       A + (long)(row0 + row) * KDIM + k0 + a_chunk);
        }
#pragma unroll
        for (int r = 0; r < 4; r++) {
            int row = b_row + 8 * r;
            cp_async16(Bs_s + row * BSTRIDE + b_chunk,
                       B + (long)(k0 + row) * NDIM + col0 + b_chunk);
        }
    };

    const int NT = KDIM / BK;   // 32

    load_tiles(0, 0);
    cp_commit();

    for (int t = 0; t < NT; t++) {
        if (t + 1 < NT) {
            load_tiles((t + 1) * BK, (t + 1) & 1);
            cp_commit();
            cp_wait<1>();
        } else {
            cp_wait<0>();
        }
        __syncthreads();

        const float* As_s = As + (t & 1) * ATILE_F;
        const float* Bs_s = Bs + (t & 1) * BTILE_F;

#pragma unroll
        for (int kk = 0; kk < 4; kk++) {
            unsigned af[4][4];
#pragma unroll
            for (int mt = 0; mt < 4; mt++) {
                const float* p = As_s + (wm * 64 + mt * 16 + grp) * ASTRIDE + kk * 8 + tin;
                af[mt][0] = __float_as_uint(p[0]);
                af[mt][1] = __float_as_uint(p[8 * ASTRIDE]);
                af[mt][2] = __float_as_uint(p[4]);
                af[mt][3] = __float_as_uint(p[8 * ASTRIDE + 4]);
            }
            unsigned bf[4][2];
#pragma unroll
            for (int nt = 0; nt < 4; nt++) {
                const float* p = Bs_s + (kk * 8 + tin) * BSTRIDE + wn * 32 + nt * 8 + grp;
                bf[nt][0] = __float_as_uint(p[0]);
                bf[nt][1] = __float_as_uint(p[4 * BSTRIDE]);
            }
#pragma unroll
            for (int mt = 0; mt < 4; mt++)
#pragma unroll
                for (int nt = 0; nt < 4; nt++)
                    mma_tf32(acc[mt][nt], af[mt], bf[nt]);
        }
        __syncthreads();
    }

    // ---- epilogue: float2 stores ----
#pragma unroll
    for (int mt = 0; mt < 4; mt++) {
        const int row = row0 + wm * 64 + mt * 16 + grp;
#pragma unroll
        for (int nt = 0; nt < 4; nt++) {
            const int col = col0 + wn * 32 + nt * 8 + tin * 2;
            float4 v = acc[mt][nt];
            *(float2*)(C + (long)row * NDIM + col)       = make_float2(v.x, v.y);
            *(float2*)(C + (long)(row + 8) * NDIM + col) = make_float2(v.z, v.w);
        }
    }
}

// ---------------------------------------------------------------------------
// premix: xk/xv/xr = tf32( x*mix + last_x*(1-mix) )
// ---------------------------------------------------------------------------
__global__ void __launch_bounds__(256)
premix_kernel(const float* __restrict__ x, const float* __restrict__ lx,
              const float* __restrict__ mk, const float* __restrict__ mv,
              const float* __restrict__ mr)
{
    const long i = ((long)blockIdx.x * 256 + threadIdx.x) * 4;
    const int c = (int)(i & (DIM - 1));

    float4 xv4 = *(const float4*)(x + i);
    float4 lv4 = *(const float4*)(lx + i);
    float4 m;
    float4 o;

    m = *(const float4*)(mk + c);
    o.x = tf32_rna(fmaf(xv4.x - lv4.x, m.x, lv4.x));
    o.y = tf32_rna(fmaf(xv4.y - lv4.y, m.y, lv4.y));
    o.z = tf32_rna(fmaf(xv4.z - lv4.z, m.z, lv4.z));
    o.w = tf32_rna(fmaf(xv4.w - lv4.w, m.w, lv4.w));
    *(float4*)(g_xk + i) = o;

    m = *(const float4*)(mv + c);
    o.x = tf32_rna(fmaf(xv4.x - lv4.x, m.x, lv4.x));
    o.y = tf32_rna(fmaf(xv4.y - lv4.y, m.y, lv4.y));
    o.z = tf32_rna(fmaf(xv4.z - lv4.z, m.z, lv4.z));
    o.w = tf32_rna(fmaf(xv4.w - lv4.w, m.w, lv4.w));
    *(float4*)(g_xv + i) = o;

    m = *(const float4*)(mr + c);
    o.x = tf32_rna(fmaf(xv4.x - lv4.x, m.x, lv4.x));
    o.y = tf32_rna(fmaf(xv4.y - lv4.y, m.y, lv4.y));
    o.z = tf32_rna(fmaf(xv4.z - lv4.z, m.z, lv4.z));
    o.w = tf32_rna(fmaf(xv4.w - lv4.w, m.w, lv4.w));
    *(float4*)(g_xr + i) = o;
}

// ---------------------------------------------------------------------------
// weight conversion to tf32
// ---------------------------------------------------------------------------
__global__ void __launch_bounds__(256)
cvtw_kernel(const float* __restrict__ Wk, const float* __restrict__ Wv,
            const float* __restrict__ Wr, const float* __restrict__ Wout)
{
    const float* src;
    if (blockIdx.z == 0)      src = Wk;
    else if (blockIdx.z == 1) src = Wv;
    else if (blockIdx.z == 2) src = Wr;
    else                      src = Wout;
    float* dst = g_W[blockIdx.z];

    const long i = ((long)blockIdx.x * 256 + threadIdx.x) * 4;
    float4 v = *(const float4*)(src + i);
    v.x = tf32_rna(v.x); v.y = tf32_rna(v.y);
    v.z = tf32_rna(v.z); v.w = tf32_rna(v.w);
    *(float4*)(dst + i) = v;
}

// ---------------------------------------------------------------------------
// elementwise RWKV recurrence
// ---------------------------------------------------------------------------
__global__ void __launch_bounds__(256)
rwkv_ew_kernel(const float* __restrict__ last_num, const float* __restrict__ last_den,
               const float* __restrict__ decay, const float* __restrict__ bonus,
               float* __restrict__ num_out, float* __restrict__ den_out)
{
    const long i = ((long)blockIdx.x * 256 + threadIdx.x) * 4;
    const int a = (int)(i & (ADIM - 1));

    float4 kk = *(const float4*)(g_K + i);
    float4 vv = *(const float4*)(g_V + i);
    float4 rp = *(const float4*)(g_R + i);
    float4 ln = *(const float4*)(last_num + i);
    float4 ld = *(const float4*)(last_den + i);
    float4 bo = *(const float4*)(bonus + a);
    float4 de = *(const float4*)(decay + a);

    float4 rw, no, dn;
    {
        const float* kp = &kk.x; const float* vp = &vv.x; const float* rpp = &rp.x;
        const float* lnp = &ln.x; const float* ldp = &ld.x;
        const float* bop = &bo.x; const float* dep = &de.x;
        float* rwp = &rw.x; float* nop = &no.x; float* dnp = &dn.x;
#pragma unroll
        for (int t = 0; t < 4; t++) {
            float k = kp[t], v = vp[t];
            float ebk = expf(bop[t] + k);
            float wkv = (lnp[t] + ebk * v) / (ldp[t] + ebk);
            float r = 1.0f / (1.0f + expf(-rpp[t]));
            rwp[t] = tf32_rna(r * wkv);            // feeds tf32 GEMM
            float w = expf(-expf(dep[t]));
            float ek = expf(k);
            nop[t] = w * lnp[t] + ek * v;
            dnp[t] = w * ldp[t] + ek;
        }
    }
    *(float4*)(g_rwkv + i)  = rw;
    *(float4*)(num_out + i) = no;
    *(float4*)(den_out + i) = dn;
}

// ---------------------------------------------------------------------------
// Launch
// Inputs: x, last_x, last_num, last_den, mix_k, mix_v, mix_r, decay, bonus,
//         Wk, Wv, Wr, Wout
// Output: concat(hidden[B,D], x[B,D], num[B,A], den[B,A]) fp32
// ---------------------------------------------------------------------------
extern "C" void kernel_launch(void* const* d_in, const int* in_sizes, int n_in,
                              void* d_out, int out_size)
{
    const float* x        = (const float*)d_in[0];
    const float* last_x   = (const float*)d_in[1];
    const float* last_num = (const float*)d_in[2];
    const float* last_den = (const float*)d_in[3];
    const float* mix_k    = (const float*)d_in[4];
    const float* mix_v    = (const float*)d_in[5];
    const float* mix_r    = (const float*)d_in[6];
    const float* decay    = (const float*)d_in[7];
    const float* bonus    = (const float*)d_in[8];
    const float* Wk       = (const float*)d_in[9];
    const float* Wv       = (const float*)d_in[10];
    const float* Wr       = (const float*)d_in[11];
    const float* Wout     = (const float*)d_in[12];

    float* out = (float*)d_out;
    const long BD = (long)BATCH * DIM;
    float* hidden_out = out;
    float* x_out      = out + BD;
    float* num_out    = out + 2 * BD;
    float* den_out    = out + 3 * BD;

    static bool attr_set = false;
    if (!attr_set) {
        cudaFuncSetAttribute(gemm_tf32_kernel,
                             cudaFuncAttributeMaxDynamicSharedMemorySize, SMEM_BYTES);
        attr_set = true;
    }

    // device scratch symbol addresses (host needs them as raw pointers)
    float *p_xk, *p_xv, *p_xr, *p_K, *p_V, *p_R, *p_rwkv, *p_W;
    cudaGetSymbolAddress((void**)&p_xk, g_xk);
    cudaGetSymbolAddress((void**)&p_xv, g_xv);
    cudaGetSymbolAddress((void**)&p_xr, g_xr);
    cudaGetSymbolAddress((void**)&p_K, g_K);
    cudaGetSymbolAddress((void**)&p_V, g_V);
    cudaGetSymbolAddress((void**)&p_R, g_R);
    cudaGetSymbolAddress((void**)&p_rwkv, g_rwkv);
    cudaGetSymbolAddress((void**)&p_W, g_W);

    // 1) premix (tf32-rounded mixed activations)
    premix_kernel<<<(unsigned)(BD / 4 / 256), 256>>>(x, last_x, mix_k, mix_v, mix_r);

    // 2) weight conversion (tiny)
    dim3 gw((KDIM * NDIM) / 4 / 256, 1, 4);
    cvtw_kernel<<<gw, 256>>>(Wk, Wv, Wr, Wout);

    // 3) K/V/R projections (one fused launch, z-indexed)
    dim3 block(NTHREADS);
    dim3 grid1(NDIM / BN, BATCH / BM, 3);
    gemm_tf32_kernel<<<grid1, block, SMEM_BYTES>>>(
        p_xk, p_xv, p_xr,
        p_W + 0 * (long)KDIM * NDIM, p_W + 1 * (long)KDIM * NDIM, p_W + 2 * (long)KDIM * NDIM,
        p_K, p_V, p_R);

    // 4) elementwise recurrence
    rwkv_ew_kernel<<<(unsigned)(BD / 4 / 256), 256>>>(last_num, last_den, decay, bonus,
                                                      num_out, den_out);

    // 5) hidden = rwkv @ Wout
    dim3 grid2(NDIM / BN, BATCH / BM, 1);
    gemm_tf32_kernel<<<grid2, block, SMEM_BYTES>>>(
        p_rwkv, p_rwkv, p_rwkv,
        p_W + 3 * (long)KDIM * NDIM, p_W + 3 * (long)KDIM * NDIM, p_W + 3 * (long)KDIM * NDIM,
        hidden_out, hidden_out, hidden_out);

    // 6) passthrough x
    cudaMemcpyAsync(x_out, x, BD * sizeof(float), cudaMemcpyDeviceToDevice);
}

// round 4
// speedup vs baseline: 7.4504x; 2.1075x over previous
#include <cuda_runtime.h>
#include <cstdint>

// Problem dims (fixed)
#define BATCH 16384
#define DIM   1024

// ---- tcgen05 GEMM tiling ----
#define BM2 256            // M rows per CTA (two M=128 MMAs)
#define BN2 256            // N cols per CTA (one N=256 MMA)
#define BK2 32             // K floats per tile (128 bytes = SW128 row)
#define NT  32             // 1024 / 32 k-tiles
#define STAGES 3
#define ASZ 32768          // 256 rows * 128B
#define BSZ 32768          // 256 rows * 128B
#define A_OFF 1024
#define B_OFF (A_OFF + STAGES * ASZ)
#define GEMM_SMEM (B_OFF + STAGES * BSZ)    // 197632 B
#define MBAR_OFF 16

// idesc: D=F32(1<<4), A=TF32(2<<7), B=TF32(2<<10), N=256 (32<<17), M=128 (8<<24)
#define IDESC_TF32 ((1u<<4) | (2u<<7) | (2u<<10) | (32u<<17) | (8u<<24))

// Scratch (device globals — allocation-free)
__device__ float g_xk[BATCH * DIM];
__device__ float g_xv[BATCH * DIM];
__device__ float g_xr[BATCH * DIM];
__device__ float g_K[BATCH * DIM];
__device__ float g_V[BATCH * DIM];
__device__ float g_R[BATCH * DIM];
__device__ float g_rwkv[BATCH * DIM];
__device__ float g_Wt[4 * DIM * DIM];   // tf32, TRANSPOSED: [N, K] K-major

// ---------------------------------------------------------------------------
// helpers (arch-portable)
// ---------------------------------------------------------------------------
__device__ __forceinline__ float tf32_rna(float x) {
    unsigned u;
    asm("cvt.rna.tf32.f32 %0, %1;" : "=r"(u) : "f"(x));
    return __uint_as_float(u);
}
__device__ __forceinline__ uint32_t smem_u32(const void* p) {
    return (uint32_t)__cvta_generic_to_shared(p);
}
__device__ __forceinline__ void cp_async16(uint32_t smem_addr, const void* gmem_ptr) {
    asm volatile("cp.async.cg.shared.global [%0], [%1], 16;\n" :: "r"(smem_addr), "l"(gmem_ptr));
}
__device__ __forceinline__ void cp_commit() { asm volatile("cp.async.commit_group;\n"); }
template <int N> __device__ __forceinline__ void cp_wait() {
    asm volatile("cp.async.wait_group %0;\n" :: "n"(N));
}
__device__ __forceinline__ void mbar_init(uint32_t a, uint32_t cnt) {
    asm volatile("mbarrier.init.shared.b64 [%0], %1;" :: "r"(a), "r"(cnt) : "memory");
}
__device__ __forceinline__ void mbar_wait(uint32_t a, uint32_t parity) {
    asm volatile(
        "{\n\t.reg .pred P;\n"
        "WL%=:\n\t"
        "mbarrier.try_wait.parity.acquire.cta.shared::cta.b64 P, [%0], %1, 0x989680;\n\t"
        "@P bra WD%=;\n\t"
        "bra WL%=;\n"
        "WD%=:\n\t}"
        :: "r"(a), "r"(parity) : "memory");
}

// ---------------------------------------------------------------------------
// tcgen05 helpers — sm_103a ONLY (guarded so the generic compute_103 PTX pass
// never sees tcgen05 instructions; the sm_103a cubin carries the real code)
// ---------------------------------------------------------------------------
#if defined(__CUDA_ARCH_FEAT_SM103_ALL) || defined(__CUDA_ARCH_FEAT_SM100_ALL)
#define HAS_TCGEN05 1
#else
#define HAS_TCGEN05 0
#endif

#if HAS_TCGEN05
__device__ __forceinline__ uint32_t elect_one() {
    uint32_t p;
    asm volatile("{\n.reg .pred P;\nelect.sync _|P, 0xFFFFFFFF;\nselp.b32 %0, 1, 0, P;\n}" : "=r"(p));
    return p;
}
// 64-bit smem descriptor: SW128, version=1 (Blackwell), LBO=1, SBO=64 (K-major)
__device__ __forceinline__ uint64_t make_desc(uint32_t addr) {
    const uint64_t base = (uint64_t(2) << 61) | (uint64_t(1) << 46)
                        | (uint64_t(64) << 32) | (uint64_t(1) << 16);
    return base | ((uint64_t)(addr >> 4) & 0x3FFF);
}
__device__ __forceinline__ void mma_tf32_ss(uint32_t d, uint64_t ad, uint64_t bd,
                                            uint32_t idesc, uint32_t en) {
    asm volatile(
        "{\n\t.reg .pred p;\n\t"
        "setp.ne.u32 p, %5, 0;\n\t"
        "tcgen05.mma.cta_group::1.kind::tf32 [%0], %1, %2, %3, {%4, %4, %4, %4}, p;\n\t}"
        :: "r"(d), "l"(ad), "l"(bd), "r"(idesc), "r"(0u), "r"(en) : "memory");
}
__device__ __forceinline__ void tc_commit(uint32_t mbar) {
    asm volatile(
        "tcgen05.commit.cta_group::1.mbarrier::arrive::one.shared::cluster.b64 [%0];"
        :: "r"(mbar) : "memory");
}
#endif

// ---------------------------------------------------------------------------
// tcgen05 tf32 GEMM: C[B*, 1024] = A[B*, 1024] @ Wt^T   (Wt is [N,K] K-major)
// CTA computes 256x256 tile. blockIdx.z selects A/B/C triple.
// ---------------------------------------------------------------------------
__global__ void __launch_bounds__(256, 1)
gemm_tc_kernel(const float* __restrict__ A0, const float* __restrict__ A1,
               const float* __restrict__ A2,
               const float* __restrict__ B0, const float* __restrict__ B1,
               const float* __restrict__ B2,
               float* __restrict__ C0, float* __restrict__ C1,
               float* __restrict__ C2)
{
#if HAS_TCGEN05
    const float* A;
    const float* B;
    float* C;
    if (blockIdx.z == 0)      { A = A0; B = B0; C = C0; }
    else if (blockIdx.z == 1) { A = A1; B = B1; C = C1; }
    else                      { A = A2; B = B2; C = C2; }

    extern __shared__ char smem[];
    const uint32_t sb = smem_u32(smem);

    const int tid = threadIdx.x;
    const int row0 = blockIdx.y * BM2;
    const int col0 = blockIdx.x * BN2;

    // TMEM alloc (512 cols): warp 0, collective
    if (tid < 32) {
        asm volatile("tcgen05.alloc.cta_group::1.sync.aligned.shared::cta.b32 [%0], %1;"
                     :: "r"(sb), "r"(512u) : "memory");
    }
    if (tid == 0) {
#pragma unroll
        for (int s = 0; s < STAGES; s++) mbar_init(sb + MBAR_OFF + s * 16, 1);
    }
    __syncthreads();
    uint32_t tmem;
    asm volatile("ld.shared.b32 %0, [%1];" : "=r"(tmem) : "r"(sb));

    // ---- tile loader: A 256x32f, B 256x32f, SW128 swizzle, cp.async 16B ----
    auto load_tile = [&](int t, int stage) {
        const int k0 = t * BK2;
        const uint32_t as = sb + A_OFF + stage * ASZ;
        const uint32_t bs = sb + B_OFF + stage * BSZ;
#pragma unroll
        for (int j = 0; j < 8; j++) {
            int i = tid + 256 * j;          // 0..2047
            int row = i >> 3, c = i & 7;
            cp_async16(as + row * 128 + ((c ^ (row & 7)) << 4),
                       A + (long)(row0 + row) * DIM + k0 + c * 4);
        }
#pragma unroll
        for (int j = 0; j < 8; j++) {
            int i = tid + 256 * j;
            int row = i >> 3, c = i & 7;
            cp_async16(bs + row * 128 + ((c ^ (row & 7)) << 4),
                       B + (long)(col0 + row) * DIM + k0 + c * 4);
        }
        cp_commit();
    };

    // prologue: tiles 0, 1
    load_tile(0, 0);
    load_tile(1, 1);

    for (int u = 0; u < NT; u++) {
        // tile u ready
        if (u == NT - 1) cp_wait<0>(); else cp_wait<1>();
        __syncthreads();

        // MMA issue (warp 0 elect)
        if (tid < 32) {
            asm volatile("fence.proxy.async.shared::cta;" ::: "memory");
            if (elect_one()) {
                const int st = u % STAGES;
                uint64_t ad0 = make_desc(sb + A_OFF + st * ASZ);
                uint64_t ad1 = make_desc(sb + A_OFF + st * ASZ + 16384);
                uint64_t bd  = make_desc(sb + B_OFF + st * BSZ);
#pragma unroll
                for (int ks = 0; ks < 4; ks++) {
                    uint32_t en = (u == 0 && ks == 0) ? 0u : 1u;
                    mma_tf32_ss(tmem,        ad0 + ks * 2, bd + ks * 2, IDESC_TF32, en);
                    mma_tf32_ss(tmem + 256,  ad1 + ks * 2, bd + ks * 2, IDESC_TF32, en);
                }
                tc_commit(sb + MBAR_OFF + st * 16);
            }
        }

        // prefetch tile u+2 into stage (u+2)%3 (freed by MMA of tile u-1)
        if (u + 2 < NT) {
            if (u >= 1) {
                const int t = u - 1;
                mbar_wait(sb + MBAR_OFF + (t % STAGES) * 16, (uint32_t)((t / STAGES) & 1));
            }
            load_tile(u + 2, (u + 2) % STAGES);
        }
    }

    // wait for final MMA (tile NT-1)
    mbar_wait(sb + MBAR_OFF + ((NT - 1) % STAGES) * 16, (uint32_t)(((NT - 1) / STAGES) & 1));
    asm volatile("tcgen05.fence::after_thread_sync;" ::: "memory");

    // ---- epilogue: 8 warps; warps 0-3 -> D0 (rows 0-127), 4-7 -> D1 ----
    {
        const int w = tid >> 5, lane = tid & 31;
        const uint32_t woff = (uint32_t)(w & 3) << 21;
        const uint32_t dbase = tmem + ((w >> 2) ? 256u : 0u) + woff;
        const int grow = row0 + (w >> 2) * 128 + (w & 3) * 32 + lane;
        float* crow = C + (long)grow * DIM + col0;
#pragma unroll
        for (int cb = 0; cb < 256; cb += 32) {
            uint32_t r[32];
            asm volatile(
                "tcgen05.ld.sync.aligned.32x32b.x32.b32 "
                "{%0,%1,%2,%3,%4,%5,%6,%7,%8,%9,%10,%11,%12,%13,%14,%15,"
                "%16,%17,%18,%19,%20,%21,%22,%23,%24,%25,%26,%27,%28,%29,%30,%31}, [%32];"
                : "=r"(r[0]), "=r"(r[1]), "=r"(r[2]), "=r"(r[3]),
                  "=r"(r[4]), "=r"(r[5]), "=r"(r[6]), "=r"(r[7]),
                  "=r"(r[8]), "=r"(r[9]), "=r"(r[10]), "=r"(r[11]),
                  "=r"(r[12]), "=r"(r[13]), "=r"(r[14]), "=r"(r[15]),
                  "=r"(r[16]), "=r"(r[17]), "=r"(r[18]), "=r"(r[19]),
                  "=r"(r[20]), "=r"(r[21]), "=r"(r[22]), "=r"(r[23]),
                  "=r"(r[24]), "=r"(r[25]), "=r"(r[26]), "=r"(r[27]),
                  "=r"(r[28]), "=r"(r[29]), "=r"(r[30]), "=r"(r[31])
                : "r"(dbase + cb));
            asm volatile("tcgen05.wait::ld.sync.aligned;" ::: "memory");
#pragma unroll
            for (int j = 0; j < 32; j += 4)
                *(float4*)(crow + cb + j) =
                    make_float4(__uint_as_float(r[j]), __uint_as_float(r[j + 1]),
                                __uint_as_float(r[j + 2]), __uint_as_float(r[j + 3]));
        }
    }

    __syncthreads();
    if (tid < 32) {
        asm volatile("tcgen05.relinquish_alloc_permit.cta_group::1.sync.aligned;");
        asm volatile("tcgen05.dealloc.cta_group::1.sync.aligned.b32 %0, %1;"
                     :: "r"(tmem), "r"(512u));
    }
#endif  // HAS_TCGEN05
}

// ---------------------------------------------------------------------------
// premix: xk/xv/xr = tf32( lerp(last_x, x, mix) )
// ---------------------------------------------------------------------------
__global__ void __launch_bounds__(256)
premix_kernel(const float* __restrict__ x, const float* __restrict__ lx,
              const float* __restrict__ mk, const float* __restrict__ mv,
              const float* __restrict__ mr)
{
    const long i = ((long)blockIdx.x * 256 + threadIdx.x) * 4;
    const int c = (int)(i & (DIM - 1));
    float4 xv4 = *(const float4*)(x + i);
    float4 lv4 = *(const float4*)(lx + i);
    float4 m, o;

    m = *(const float4*)(mk + c);
    o.x = tf32_rna(fmaf(xv4.x - lv4.x, m.x, lv4.x));
    o.y = tf32_rna(fmaf(xv4.y - lv4.y, m.y, lv4.y));
    o.z = tf32_rna(fmaf(xv4.z - lv4.z, m.z, lv4.z));
    o.w = tf32_rna(fmaf(xv4.w - lv4.w, m.w, lv4.w));
    *(float4*)(g_xk + i) = o;

    m = *(const float4*)(mv + c);
    o.x = tf32_rna(fmaf(xv4.x - lv4.x, m.x, lv4.x));
    o.y = tf32_rna(fmaf(xv4.y - lv4.y, m.y, lv4.y));
    o.z = tf32_rna(fmaf(xv4.z - lv4.z, m.z, lv4.z));
    o.w = tf32_rna(fmaf(xv4.w - lv4.w, m.w, lv4.w));
    *(float4*)(g_xv + i) = o;

    m = *(const float4*)(mr + c);
    o.x = tf32_rna(fmaf(xv4.x - lv4.x, m.x, lv4.x));
    o.y = tf32_rna(fmaf(xv4.y - lv4.y, m.y, lv4.y));
    o.z = tf32_rna(fmaf(xv4.z - lv4.z, m.z, lv4.z));
    o.w = tf32_rna(fmaf(xv4.w - lv4.w, m.w, lv4.w));
    *(float4*)(g_xr + i) = o;
}

// ---------------------------------------------------------------------------
// weight convert + transpose: g_Wt[z][n*1024 + k] = tf32(W_z[k*1024 + n])
// ---------------------------------------------------------------------------
__global__ void __launch_bounds__(256)
cvtw_kernel(const float* __restrict__ Wk, const float* __restrict__ Wv,
            const float* __restrict__ Wr, const float* __restrict__ Wout)
{
    __shared__ float t[32][33];
    const float* src;
    if (blockIdx.z == 0)      src = Wk;
    else if (blockIdx.z == 1) src = Wv;
    else if (blockIdx.z == 2) src = Wr;
    else                      src = Wout;
    float* dst = g_Wt + (long)blockIdx.z * DIM * DIM;

    const int kb = blockIdx.x * 32, nb = blockIdx.y * 32;
    const int tx = threadIdx.x & 31, ty = threadIdx.x >> 5;   // 32 x 8
#pragma unroll
    for (int r = ty; r < 32; r += 8)
        t[r][tx] = tf32_rna(src[(long)(kb + r) * DIM + nb + tx]);
    __syncthreads();
#pragma unroll
    for (int r = ty; r < 32; r += 8)
        dst[(long)(nb + r) * DIM + kb + tx] = t[tx][r];
}

// ---------------------------------------------------------------------------
// elementwise RWKV recurrence
// ---------------------------------------------------------------------------
__global__ void __launch_bounds__(256)
rwkv_ew_kernel(const float* __restrict__ last_num, const float* __restrict__ last_den,
               const float* __restrict__ decay, const float* __restrict__ bonus,
               float* __restrict__ num_out, float* __restrict__ den_out)
{
    const long i = ((long)blockIdx.x * 256 + threadIdx.x) * 4;
    const int a = (int)(i & (DIM - 1));

    float4 kk = *(const float4*)(g_K + i);
    float4 vv = *(const float4*)(g_V + i);
    float4 rp = *(const float4*)(g_R + i);
    float4 ln = *(const float4*)(last_num + i);
    float4 ld = *(const float4*)(last_den + i);
    float4 bo = *(const float4*)(bonus + a);
    float4 de = *(const float4*)(decay + a);

    float4 rw, no, dn;
    {
        const float* kp = &kk.x; const float* vp = &vv.x; const float* rpp = &rp.x;
        const float* lnp = &ln.x; const float* ldp = &ld.x;
        const float* bop = &bo.x; const float* dep = &de.x;
        float* rwp = &rw.x; float* nop = &no.x; float* dnp = &dn.x;
#pragma unroll
        for (int t = 0; t < 4; t++) {
            float k = kp[t], v = vp[t];
            float ebk = expf(bop[t] + k);
            float wkv = (lnp[t] + ebk * v) / (ldp[t] + ebk);
            float r = 1.0f / (1.0f + expf(-rpp[t]));
            rwp[t] = tf32_rna(r * wkv);
            float w = expf(-expf(dep[t]));
            float ek = expf(k);
            nop[t] = w * lnp[t] + ek * v;
            dnp[t] = w * ldp[t] + ek;
        }
    }
    *(float4*)(g_rwkv + i)  = rw;
    *(float4*)(num_out + i) = no;
    *(float4*)(den_out + i) = dn;
}

// ---------------------------------------------------------------------------
// Launch
// ---------------------------------------------------------------------------
extern "C" void kernel_launch(void* const* d_in, const int* in_sizes, int n_in,
                              void* d_out, int out_size)
{
    const float* x        = (const float*)d_in[0];
    const float* last_x   = (const float*)d_in[1];
    const float* last_num = (const float*)d_in[2];
    const float* last_den = (const float*)d_in[3];
    const float* mix_k    = (const float*)d_in[4];
    const float* mix_v    = (const float*)d_in[5];
    const float* mix_r    = (const float*)d_in[6];
    const float* decay    = (const float*)d_in[7];
    const float* bonus    = (const float*)d_in[8];
    const float* Wk       = (const float*)d_in[9];
    const float* Wv       = (const float*)d_in[10];
    const float* Wr       = (const float*)d_in[11];
    const float* Wout     = (const float*)d_in[12];

    float* out = (float*)d_out;
    const long BD = (long)BATCH * DIM;
    float* hidden_out = out;
    float* x_out      = out + BD;
    float* num_out    = out + 2 * BD;
    float* den_out    = out + 3 * BD;

    static bool attr_set = false;
    if (!attr_set) {
        cudaFuncSetAttribute(gemm_tc_kernel,
                             cudaFuncAttributeMaxDynamicSharedMemorySize, GEMM_SMEM);
        attr_set = true;
    }

    float *p_xk, *p_xv, *p_xr, *p_K, *p_V, *p_R, *p_rwkv, *p_Wt;
    cudaGetSymbolAddress((void**)&p_xk, g_xk);
    cudaGetSymbolAddress((void**)&p_xv, g_xv);
    cudaGetSymbolAddress((void**)&p_xr, g_xr);
    cudaGetSymbolAddress((void**)&p_K, g_K);
    cudaGetSymbolAddress((void**)&p_V, g_V);
    cudaGetSymbolAddress((void**)&p_R, g_R);
    cudaGetSymbolAddress((void**)&p_rwkv, g_rwkv);
    cudaGetSymbolAddress((void**)&p_Wt, g_Wt);

    // 1) premix
    premix_kernel<<<(unsigned)(BD / 4 / 256), 256>>>(x, last_x, mix_k, mix_v, mix_r);

    // 2) weight convert+transpose (tiny)
    dim3 gw(DIM / 32, DIM / 32, 4);
    cvtw_kernel<<<gw, 256>>>(Wk, Wv, Wr, Wout);

    // 3) K/V/R projections
    dim3 grid1(DIM / BN2, BATCH / BM2, 3);
    gemm_tc_kernel<<<grid1, 256, GEMM_SMEM>>>(
        p_xk, p_xv, p_xr,
        p_Wt + 0L * DIM * DIM, p_Wt + 1L * DIM * DIM, p_Wt + 2L * DIM * DIM,
        p_K, p_V, p_R);

    // 4) elementwise recurrence
    rwkv_ew_kernel<<<(unsigned)(BD / 4 / 256), 256>>>(last_num, last_den, decay, bonus,
                                                      num_out, den_out);

    // 5) hidden = rwkv @ Wout
    dim3 grid2(DIM / BN2, BATCH / BM2, 1);
    gemm_tc_kernel<<<grid2, 256, GEMM_SMEM>>>(
        p_rwkv, p_rwkv, p_rwkv,
        p_Wt + 3L * DIM * DIM, p_Wt + 3L * DIM * DIM, p_Wt + 3L * DIM * DIM,
        hidden_out, hidden_out, hidden_out);

    // 6) passthrough x
    cudaMemcpyAsync(x_out, x, BD * sizeof(float), cudaMemcpyDeviceToDevice);
}